// round 3
// baseline (speedup 1.0000x reference)
#include <cuda_runtime.h>
#include <math.h>

// ---------------------------------------------------------------------------
// Problem constants
// ---------------------------------------------------------------------------
#define BB   128
#define NN   64
#define EE   128
#define NNODE (BB*NN)          // 8192
#define NEDGE (NN-1)           // 63

// ---------------------------------------------------------------------------
// Device scratch (static, no allocation)
// ---------------------------------------------------------------------------
__device__ float g_H  [NNODE*128];   // hidden after W1
__device__ float g_CAT[NNODE*256];   // [ae | attn_out]
__device__ float g_PP [NNODE*256];   // [P1 | Pa]
__device__ float g_D1 [NNODE*256];   // hidden after Wd1
__device__ float g_Wpp[256*128];     // rows 0..127: Wh1[:, :128]; rows 128..255: Wa1[:, :128]@Wq
__device__ float g_bpp[256];         // [bh1 | ba1]
__device__ float g_Wc [2*128];       // Whe @ Wh2
__device__ float g_bc [2];           // Whe @ bh2 + bhe
__device__ float g_Wh1e[128*8];      // Wh1[:, 128:135], padded to 8
__device__ float g_Wa1e[128*8];      // Wa1[:, 128:135], padded to 8
__device__ float g_ent[NNODE];

// ---------------------------------------------------------------------------
// Generic fused GEMM:  C = act(A @ W^T + bias)
// A: M x K (row stride lda), W: N x K (row stride ldw), C: M x N (row stride ldc)
// act: 0 = none, 1 = leaky_relu(0.01)
// M % 64 == 0, N % 64 == 0 assumed.
// ---------------------------------------------------------------------------
__global__ __launch_bounds__(256) void gemm_act(
    const float* __restrict__ A, int lda,
    const float* __restrict__ W, int ldw,
    const float* __restrict__ bias,
    float* __restrict__ C, int ldc,
    int M, int N, int K, int act)
{
    __shared__ float As[64][17];
    __shared__ float Ws[64][17];
    const int tid = threadIdx.x;
    const int bm = blockIdx.y * 64;
    const int bn = blockIdx.x * 64;
    const int tm = (tid >> 4) << 2;   // 0..60
    const int tn = (tid & 15) << 2;   // 0..60

    float acc[4][4];
#pragma unroll
    for (int i = 0; i < 4; i++)
#pragma unroll
        for (int j = 0; j < 4; j++) acc[i][j] = 0.f;

    for (int k0 = 0; k0 < K; k0 += 16) {
#pragma unroll
        for (int i = tid; i < 1024; i += 256) {
            int r = i >> 4, kk = i & 15;
            int kg = k0 + kk;
            As[r][kk] = (kg < K) ? A[(size_t)(bm + r) * lda + kg] : 0.f;
            Ws[r][kk] = (kg < K) ? W[(size_t)(bn + r) * ldw + kg] : 0.f;
        }
        __syncthreads();
#pragma unroll
        for (int kk = 0; kk < 16; kk++) {
            float a[4], w[4];
#pragma unroll
            for (int i = 0; i < 4; i++) a[i] = As[tm + i][kk];
#pragma unroll
            for (int j = 0; j < 4; j++) w[j] = Ws[tn + j][kk];
#pragma unroll
            for (int i = 0; i < 4; i++)
#pragma unroll
                for (int j = 0; j < 4; j++) acc[i][j] += a[i] * w[j];
        }
        __syncthreads();
    }

#pragma unroll
    for (int i = 0; i < 4; i++)
#pragma unroll
        for (int j = 0; j < 4; j++) {
            float v = acc[i][j];
            if (bias) v += bias[bn + tn + j];
            if (act == 1) v = (v > 0.f) ? v : 0.01f * v;
            C[(size_t)(bm + tm + i) * ldc + (bn + tn + j)] = v;
        }
}

// ---------------------------------------------------------------------------
// Precompute folded weights (runs every launch; deterministic, ~2 MFLOP)
// blocks 0..127 : Wpp rows 0..127   = Wh1[:, :128]
// blocks 128..255: Wpp rows 128..255 = Wa1[:, :128] @ Wq
// block 256     : Wc, bc, bpp, Wh1e, Wa1e
// ---------------------------------------------------------------------------
__global__ void precompute(
    const float* __restrict__ Wh1, const float* __restrict__ Wa1,
    const float* __restrict__ Wq,  const float* __restrict__ Whe,
    const float* __restrict__ Wh2, const float* __restrict__ bh2,
    const float* __restrict__ bhe, const float* __restrict__ bh1,
    const float* __restrict__ ba1)
{
    const int b = blockIdx.x, t = threadIdx.x;   // 128 threads
    if (b < 128) {
        g_Wpp[b * 128 + t] = Wh1[b * 135 + t];
    } else if (b < 256) {
        const int o = b - 128;
        float acc = 0.f;
        for (int j = 0; j < 128; j++) acc += Wa1[o * 135 + j] * Wq[j * 128 + t];
        g_Wpp[b * 128 + t] = acc;
    } else {
        float a0 = 0.f, a1 = 0.f;
        for (int j = 0; j < 128; j++) {
            a0 += Whe[j]       * Wh2[j * 128 + t];
            a1 += Whe[128 + j] * Wh2[j * 128 + t];
        }
        g_Wc[t] = a0; g_Wc[128 + t] = a1;
        if (t < 2) {
            float s = 0.f;
            for (int j = 0; j < 128; j++) s += Whe[t * 128 + j] * bh2[j];
            g_bc[t] = s + bhe[t];
        }
        g_bpp[t] = bh1[t]; g_bpp[128 + t] = ba1[t];
#pragma unroll
        for (int j = 0; j < 8; j++) {
            g_Wh1e[t * 8 + j] = (j < 7) ? Wh1[t * 135 + 128 + j] : 0.f;
            g_Wa1e[t * 8 + j] = (j < 7) ? Wa1[t * 135 + 128 + j] : 0.f;
        }
    }
}

// ---------------------------------------------------------------------------
// Fused per-edge kernel: one block (64 threads) per node.
// Computes edge features, hard-gate logits (via folded Wc), attention scores,
// gumbel softmax, masked softmax, combined weights, entropy, and attn_out
// (via the linearity trick: attn_out = Wv @ (sum c_k e_k) + bv * sum c_k).
// ---------------------------------------------------------------------------
__global__ __launch_bounds__(64) void edge_kernel(
    const float* __restrict__ emb,   // (8192, 9)
    const float* __restrict__ gum,   // (8192, 63, 2)
    const float* __restrict__ Wa2,   // (1,128)
    const float* __restrict__ ba2,   // (1,)
    const float* __restrict__ Wv,    // (128,7)
    const float* __restrict__ bv,    // (128,)
    float* __restrict__ out_log,
    float* __restrict__ out_dist,
    float* __restrict__ out_hw,
    float* __restrict__ out_cmb)
{
    __shared__ float P1s[128], Pas[128], Wc0s[128], Wc1s[128], Wa2s[128];
    __shared__ float Wh1e_s[128 * 8], Wa1e_s[128 * 8];
    __shared__ float s_e[64 * 8];
    __shared__ float s_sc[64], s_msk[64], s_ex[64], s_cmb[64];
    __shared__ float s_red[12];  // [0]=max [1]=den [2]=any [3]=csum [4..10]=esum

    const int node = blockIdx.x;
    const int n = node & (NN - 1);
    const int t = threadIdx.x;

    for (int i = t; i < 128; i += 64) {
        P1s[i]  = g_PP[(size_t)node * 256 + i];
        Pas[i]  = g_PP[(size_t)node * 256 + 128 + i];
        Wc0s[i] = g_Wc[i];
        Wc1s[i] = g_Wc[128 + i];
        Wa2s[i] = Wa2[i];
    }
    for (int i = t; i < 1024; i += 64) {
        Wh1e_s[i] = g_Wh1e[i];
        Wa1e_s[i] = g_Wa1e[i];
    }
    __syncthreads();

    const float* er = emb + (size_t)node * 9;
    const float pnx = er[0], pny = er[1], hnx = er[2], hny = er[3];

    float e[8];
    const bool active = (t < NEDGE);
    if (active) {
        const int j = t + (t >= n);
        const float* ej = emb + (size_t)(node - n + j) * 9;
        float dx = ej[0] - pnx, dy = ej[1] - pny;
        float sq = dx * dx + dy * dy;
        float rd = (sq > 0.f) ? sqrtf(sq) : 0.f;
        float ang = atan2f(dy, dx) - atan2f(hny, hnx);
        float ca, sa;
        sincosf(ang, &sa, &ca);
        e[0] = rd; e[1] = ca; e[2] = sa;
        e[3] = ej[2]; e[4] = ej[3]; e[5] = ej[7]; e[6] = ej[8];
        e[7] = 0.f;

        float l0 = 0.f, l1 = 0.f, sc = 0.f;
#pragma unroll 4
        for (int o = 0; o < 128; o++) {
            const float* wh = &Wh1e_s[o * 8];
            const float* wa = &Wa1e_s[o * 8];
            float h = P1s[o], a = Pas[o];
#pragma unroll
            for (int q = 0; q < 7; q++) { h += wh[q] * e[q]; a += wa[q] * e[q]; }
            h = (h > 0.f) ? h : 0.f;
            a = (a > 0.f) ? a : 0.f;
            l0 += Wc0s[o] * h;
            l1 += Wc1s[o] * h;
            sc += Wa2s[o] * a;
        }
        l0 += g_bc[0]; l1 += g_bc[1]; sc += ba2[0];

        const size_t gi = ((size_t)node * NEDGE + t) * 2;
        float g0 = gum[gi], g1 = gum[gi + 1];
        float y1 = 1.f / (1.f + expf(2.f * ((l0 + g0) - (l1 + g1))));

        const size_t oi = (size_t)node * NEDGE + t;
        out_log[oi]  = l1;
        out_dist[oi] = 12.f * rd;
        out_hw[oi]   = y1;

        s_msk[t] = (y1 > 0.5f) ? 1.f : 0.f;
        s_sc[t]  = sc;
#pragma unroll
        for (int q = 0; q < 8; q++) s_e[t * 8 + q] = e[q];
    }
    __syncthreads();

    if (t == 0) {  // deterministic serial max over masked scores
        float maxv = -1e30f, any = 0.f;
        for (int k = 0; k < NEDGE; k++)
            if (s_msk[k] > 0.f) { any = 1.f; if (s_sc[k] > maxv) maxv = s_sc[k]; }
        s_red[0] = maxv; s_red[2] = any;
    }
    __syncthreads();
    const float maxv = s_red[0], any = s_red[2];
    if (active) s_ex[t] = (s_msk[t] > 0.f) ? expf(s_sc[t] - maxv) : 0.f;
    __syncthreads();
    if (t == 0) {
        float den = 0.f;
        for (int k = 0; k < NEDGE; k++) den += s_ex[k];
        s_red[1] = den;
    }
    __syncthreads();
    const float den = s_red[1];
    if (active) {
        float c = (any > 0.f && s_msk[t] > 0.f) ? s_ex[t] / den : 0.f;
        s_cmb[t] = c;
        out_cmb[(size_t)node * NEDGE + t] = c;
    }
    __syncthreads();
    if (t < 8) {
        float s = 0.f;
        if (t < 7) {
            for (int k = 0; k < NEDGE; k++) s += s_cmb[k] * s_e[k * 8 + t];
            s_red[4 + t] = s;
        } else {
            for (int k = 0; k < NEDGE; k++) s += s_cmb[k];
            s_red[3] = s;
        }
    }
    __syncthreads();
    const float csum = s_red[3];
    if (t == 0) {
        float ent = 0.f;
        const float inv = 1.f / (csum + 1e-6f);
        for (int k = 0; k < NEDGE; k++) {
            float cw = s_cmb[k] * inv;
            ent -= cw * logf(cw + 1e-6f);
        }
        g_ent[node] = ent;
    }
    // attn_out = Wv @ esum + bv * csum  -> CAT[:, 128:256]
    for (int d = t; d < 128; d += 64) {
        float v = bv[d] * csum;
#pragma unroll
        for (int q = 0; q < 7; q++) v += Wv[d * 7 + q] * s_red[4 + q];
        g_CAT[(size_t)node * 256 + 128 + d] = v;
    }
}

// ---------------------------------------------------------------------------
// Deterministic entropy mean reduction
// ---------------------------------------------------------------------------
__global__ void ent_reduce(float* __restrict__ out_ent)
{
    __shared__ float s[256];
    const int t = threadIdx.x;
    float a = 0.f;
    for (int i = t; i < NNODE; i += 256) a += g_ent[i];
    s[t] = a;
    __syncthreads();
    for (int off = 128; off > 0; off >>= 1) {
        if (t < off) s[t] += s[t + off];
        __syncthreads();
    }
    if (t == 0) out_ent[0] = s[0] / (float)NNODE;
}

// ---------------------------------------------------------------------------
// Host launch
// ---------------------------------------------------------------------------
extern "C" void kernel_launch(void* const* d_in, const int* in_sizes, int n_in,
                              void* d_out, int out_size)
{
    const float* emb = (const float*)d_in[0];
    const float* gum = (const float*)d_in[1];
    const float* W1  = (const float*)d_in[2];
    const float* b1  = (const float*)d_in[3];
    const float* W2  = (const float*)d_in[4];
    const float* b2  = (const float*)d_in[5];
    const float* Wh1 = (const float*)d_in[6];
    const float* bh1 = (const float*)d_in[7];
    const float* Wh2 = (const float*)d_in[8];
    const float* bh2 = (const float*)d_in[9];
    const float* Whe = (const float*)d_in[10];
    const float* bhe = (const float*)d_in[11];
    const float* Wq  = (const float*)d_in[12];
    const float* Wa1 = (const float*)d_in[13];
    const float* ba1 = (const float*)d_in[14];
    const float* Wa2 = (const float*)d_in[15];
    const float* ba2 = (const float*)d_in[16];
    const float* Wv  = (const float*)d_in[17];
    const float* bv  = (const float*)d_in[18];
    const float* Wd1 = (const float*)d_in[19];
    const float* bd1 = (const float*)d_in[20];
    const float* Wd2 = (const float*)d_in[21];
    const float* bd2 = (const float*)d_in[22];

    float* out      = (float*)d_out;
    float* out_att  = out;                      // 8192*256
    float* out_log  = out_att + 2097152;        // 8192*63
    float* out_dist = out_log + 516096;         // 8192*63
    float* out_ent  = out_dist + 516096;        // 1
    float* out_hw   = out_ent + 1;              // 8192*63
    float* out_cmb  = out_hw + 516096;          // 8192*63

    float *H, *CAT, *PP, *D1, *Wpp, *bpp;
    cudaGetSymbolAddress((void**)&H,   g_H);
    cudaGetSymbolAddress((void**)&CAT, g_CAT);
    cudaGetSymbolAddress((void**)&PP,  g_PP);
    cudaGetSymbolAddress((void**)&D1,  g_D1);
    cudaGetSymbolAddress((void**)&Wpp, g_Wpp);
    cudaGetSymbolAddress((void**)&bpp, g_bpp);

    // Folded weights (must precede G3 + edge kernel)
    precompute<<<257, 128>>>(Wh1, Wa1, Wq, Whe, Wh2, bh2, bhe, bh1, ba1);

    // Node pipeline
    // G1: H = lrelu(embed @ W1^T + b1); embed = embedding[:, 4:9] (lda=9, ptr+4)
    gemm_act<<<dim3(2, 128), 256>>>(emb + 4, 9, W1, 5, b1, H, 128, NNODE, 128, 5, 1);
    // G2: AE = lrelu(H @ W2^T + b2) -> CAT[:, :128]
    gemm_act<<<dim3(2, 128), 256>>>(H, 128, W2, 128, b2, CAT, 256, NNODE, 128, 128, 1);
    // G3: [P1 | Pa] = AE @ Wpp^T + bpp
    gemm_act<<<dim3(4, 128), 256>>>(CAT, 256, Wpp, 128, bpp, PP, 256, NNODE, 256, 128, 0);

    // Edge pipeline (writes 4 output regions + CAT[:, 128:])
    edge_kernel<<<NNODE, 64>>>(emb, gum, Wa2, ba2, Wv, bv,
                               out_log, out_dist, out_hw, out_cmb);

    ent_reduce<<<1, 256>>>(out_ent);

    // Decoder
    gemm_act<<<dim3(4, 128), 256>>>(CAT, 256, Wd1, 256, bd1, D1, 256, NNODE, 256, 256, 1);
    gemm_act<<<dim3(4, 128), 256>>>(D1, 256, Wd2, 256, bd2, out_att, 256, NNODE, 256, 256, 1);

    (void)in_sizes; (void)n_in; (void)out_size;
}

// round 4
// speedup vs baseline: 1.0064x; 1.0064x over previous
#include <cuda_runtime.h>
#include <math.h>

// ---------------------------------------------------------------------------
// Problem constants
// ---------------------------------------------------------------------------
#define BB   128
#define NN   64
#define EE   128
#define NNODE (BB*NN)          // 8192
#define NEDGE (NN-1)           // 63

// ---------------------------------------------------------------------------
// Device scratch (static, no allocation)
// ---------------------------------------------------------------------------
__device__ float g_H  [NNODE*128];   // hidden after W1
__device__ float g_CAT[NNODE*256];   // [ae | attn_out]
__device__ float g_PP [NNODE*256];   // [P1 | Pa]
__device__ float g_D1 [NNODE*256];   // hidden after Wd1
__device__ float g_Wpp[256*128];     // rows 0..127: Wh1[:, :128]; rows 128..255: Wa1[:, :128]@Wq
__device__ float g_bpp[256];         // [bh1 | ba1]
__device__ float g_Wc [2*128];       // Whe @ Wh2
__device__ float g_bc [2];           // Whe @ bh2 + bhe
__device__ float g_Wh1e[128*8];      // Wh1[:, 128:135], padded to 8
__device__ float g_Wa1e[128*8];      // Wa1[:, 128:135], padded to 8
__device__ float g_ent[NNODE];

// ---------------------------------------------------------------------------
// Generic fused GEMM:  C = act(A @ W^T + bias)
// A: M x K (row stride lda), W: N x K (row stride ldw), C: M x N (row stride ldc)
// act: 0 = none, 1 = leaky_relu(0.01)
// M % 64 == 0, N % 64 == 0 assumed.
// ---------------------------------------------------------------------------
__global__ __launch_bounds__(256) void gemm_act(
    const float* __restrict__ A, int lda,
    const float* __restrict__ W, int ldw,
    const float* __restrict__ bias,
    float* __restrict__ C, int ldc,
    int M, int N, int K, int act)
{
    __shared__ float As[64][17];
    __shared__ float Ws[64][17];
    const int tid = threadIdx.x;
    const int bm = blockIdx.y * 64;
    const int bn = blockIdx.x * 64;
    const int tm = (tid >> 4) << 2;   // 0..60
    const int tn = (tid & 15) << 2;   // 0..60

    float acc[4][4];
#pragma unroll
    for (int i = 0; i < 4; i++)
#pragma unroll
        for (int j = 0; j < 4; j++) acc[i][j] = 0.f;

    for (int k0 = 0; k0 < K; k0 += 16) {
#pragma unroll
        for (int i = tid; i < 1024; i += 256) {
            int r = i >> 4, kk = i & 15;
            int kg = k0 + kk;
            As[r][kk] = (kg < K) ? A[(size_t)(bm + r) * lda + kg] : 0.f;
            Ws[r][kk] = (kg < K) ? W[(size_t)(bn + r) * ldw + kg] : 0.f;
        }
        __syncthreads();
#pragma unroll
        for (int kk = 0; kk < 16; kk++) {
            float a[4], w[4];
#pragma unroll
            for (int i = 0; i < 4; i++) a[i] = As[tm + i][kk];
#pragma unroll
            for (int j = 0; j < 4; j++) w[j] = Ws[tn + j][kk];
#pragma unroll
            for (int i = 0; i < 4; i++)
#pragma unroll
                for (int j = 0; j < 4; j++) acc[i][j] += a[i] * w[j];
        }
        __syncthreads();
    }

#pragma unroll
    for (int i = 0; i < 4; i++)
#pragma unroll
        for (int j = 0; j < 4; j++) {
            float v = acc[i][j];
            if (bias) v += bias[bn + tn + j];
            if (act == 1) v = (v > 0.f) ? v : 0.01f * v;
            C[(size_t)(bm + tm + i) * ldc + (bn + tn + j)] = v;
        }
}

// ---------------------------------------------------------------------------
// Precompute folded weights (runs every launch; deterministic, ~2 MFLOP)
// blocks 0..127 : Wpp rows 0..127   = Wh1[:, :128]
// blocks 128..255: Wpp rows 128..255 = Wa1[:, :128] @ Wq
// block 256     : Wc, bc, bpp, Wh1e, Wa1e
// ---------------------------------------------------------------------------
__global__ void precompute(
    const float* __restrict__ Wh1, const float* __restrict__ Wa1,
    const float* __restrict__ Wq,  const float* __restrict__ Whe,
    const float* __restrict__ Wh2, const float* __restrict__ bh2,
    const float* __restrict__ bhe, const float* __restrict__ bh1,
    const float* __restrict__ ba1)
{
    const int b = blockIdx.x, t = threadIdx.x;   // 128 threads
    if (b < 128) {
        g_Wpp[b * 128 + t] = Wh1[b * 135 + t];
    } else if (b < 256) {
        const int o = b - 128;
        float acc = 0.f;
        for (int j = 0; j < 128; j++) acc += Wa1[o * 135 + j] * Wq[j * 128 + t];
        g_Wpp[b * 128 + t] = acc;
    } else {
        float a0 = 0.f, a1 = 0.f;
        for (int j = 0; j < 128; j++) {
            a0 += Whe[j]       * Wh2[j * 128 + t];
            a1 += Whe[128 + j] * Wh2[j * 128 + t];
        }
        g_Wc[t] = a0; g_Wc[128 + t] = a1;
        if (t < 2) {
            float s = 0.f;
            for (int j = 0; j < 128; j++) s += Whe[t * 128 + j] * bh2[j];
            g_bc[t] = s + bhe[t];
        }
        g_bpp[t] = bh1[t]; g_bpp[128 + t] = ba1[t];
#pragma unroll
        for (int j = 0; j < 8; j++) {
            g_Wh1e[t * 8 + j] = (j < 7) ? Wh1[t * 135 + 128 + j] : 0.f;
            g_Wa1e[t * 8 + j] = (j < 7) ? Wa1[t * 135 + 128 + j] : 0.f;
        }
    }
}

// ---------------------------------------------------------------------------
// Fused per-edge kernel: one block (64 threads) per node.
// Computes edge features, hard-gate logits (via folded Wc), attention scores,
// gumbel softmax, masked softmax, combined weights, entropy, and attn_out
// (via the linearity trick: attn_out = Wv @ (sum c_k e_k) + bv * sum c_k).
// ---------------------------------------------------------------------------
__global__ __launch_bounds__(64) void edge_kernel(
    const float* __restrict__ emb,   // (8192, 9)
    const float* __restrict__ gum,   // (8192, 63, 2)
    const float* __restrict__ Wa2,   // (1,128)
    const float* __restrict__ ba2,   // (1,)
    const float* __restrict__ Wv,    // (128,7)
    const float* __restrict__ bv,    // (128,)
    float* __restrict__ out_log,
    float* __restrict__ out_dist,
    float* __restrict__ out_hw,
    float* __restrict__ out_cmb)
{
    __shared__ float P1s[128], Pas[128], Wc0s[128], Wc1s[128], Wa2s[128];
    __shared__ float Wh1e_s[128 * 8], Wa1e_s[128 * 8];
    __shared__ float s_e[64 * 8];
    __shared__ float s_sc[64], s_msk[64], s_ex[64], s_cmb[64];
    __shared__ float s_red[12];  // [0]=max [1]=den [2]=any [3]=csum [4..10]=esum

    const int node = blockIdx.x;
    const int n = node & (NN - 1);
    const int t = threadIdx.x;

    for (int i = t; i < 128; i += 64) {
        P1s[i]  = g_PP[(size_t)node * 256 + i];
        Pas[i]  = g_PP[(size_t)node * 256 + 128 + i];
        Wc0s[i] = g_Wc[i];
        Wc1s[i] = g_Wc[128 + i];
        Wa2s[i] = Wa2[i];
    }
    for (int i = t; i < 1024; i += 64) {
        Wh1e_s[i] = g_Wh1e[i];
        Wa1e_s[i] = g_Wa1e[i];
    }
    __syncthreads();

    const float* er = emb + (size_t)node * 9;
    const float pnx = er[0], pny = er[1], hnx = er[2], hny = er[3];

    float e[8];
    const bool active = (t < NEDGE);
    if (active) {
        const int j = t + (t >= n);
        const float* ej = emb + (size_t)(node - n + j) * 9;
        float dx = ej[0] - pnx, dy = ej[1] - pny;
        float sq = dx * dx + dy * dy;
        float rd = (sq > 0.f) ? sqrtf(sq) : 0.f;
        float ang = atan2f(dy, dx) - atan2f(hny, hnx);
        float ca, sa;
        sincosf(ang, &sa, &ca);
        e[0] = rd; e[1] = ca; e[2] = sa;
        e[3] = ej[2]; e[4] = ej[3]; e[5] = ej[7]; e[6] = ej[8];
        e[7] = 0.f;

        float l0 = 0.f, l1 = 0.f, sc = 0.f;
#pragma unroll 4
        for (int o = 0; o < 128; o++) {
            const float* wh = &Wh1e_s[o * 8];
            const float* wa = &Wa1e_s[o * 8];
            float h = P1s[o], a = Pas[o];
#pragma unroll
            for (int q = 0; q < 7; q++) { h += wh[q] * e[q]; a += wa[q] * e[q]; }
            h = (h > 0.f) ? h : 0.f;
            a = (a > 0.f) ? a : 0.f;
            l0 += Wc0s[o] * h;
            l1 += Wc1s[o] * h;
            sc += Wa2s[o] * a;
        }
        l0 += g_bc[0]; l1 += g_bc[1]; sc += ba2[0];

        const size_t gi = ((size_t)node * NEDGE + t) * 2;
        float g0 = gum[gi], g1 = gum[gi + 1];
        float y1 = 1.f / (1.f + expf(2.f * ((l0 + g0) - (l1 + g1))));

        const size_t oi = (size_t)node * NEDGE + t;
        out_log[oi]  = l1;
        out_dist[oi] = 12.f * rd;
        out_hw[oi]   = y1;

        s_msk[t] = (y1 > 0.5f) ? 1.f : 0.f;
        s_sc[t]  = sc;
#pragma unroll
        for (int q = 0; q < 8; q++) s_e[t * 8 + q] = e[q];
    }
    __syncthreads();

    if (t == 0) {  // deterministic serial max over masked scores
        float maxv = -1e30f, any = 0.f;
        for (int k = 0; k < NEDGE; k++)
            if (s_msk[k] > 0.f) { any = 1.f; if (s_sc[k] > maxv) maxv = s_sc[k]; }
        s_red[0] = maxv; s_red[2] = any;
    }
    __syncthreads();
    const float maxv = s_red[0], any = s_red[2];
    if (active) s_ex[t] = (s_msk[t] > 0.f) ? expf(s_sc[t] - maxv) : 0.f;
    __syncthreads();
    if (t == 0) {
        float den = 0.f;
        for (int k = 0; k < NEDGE; k++) den += s_ex[k];
        s_red[1] = den;
    }
    __syncthreads();
    const float den = s_red[1];
    if (active) {
        float c = (any > 0.f && s_msk[t] > 0.f) ? s_ex[t] / den : 0.f;
        s_cmb[t] = c;
        out_cmb[(size_t)node * NEDGE + t] = c;
    }
    __syncthreads();
    if (t < 8) {
        float s = 0.f;
        if (t < 7) {
            for (int k = 0; k < NEDGE; k++) s += s_cmb[k] * s_e[k * 8 + t];
            s_red[4 + t] = s;
        } else {
            for (int k = 0; k < NEDGE; k++) s += s_cmb[k];
            s_red[3] = s;
        }
    }
    __syncthreads();
    const float csum = s_red[3];
    if (t == 0) {
        float ent = 0.f;
        const float inv = 1.f / (csum + 1e-6f);
        for (int k = 0; k < NEDGE; k++) {
            float cw = s_cmb[k] * inv;
            ent -= cw * logf(cw + 1e-6f);
        }
        g_ent[node] = ent;
    }
    // attn_out = Wv @ esum + bv * csum  -> CAT[:, 128:256]
    for (int d = t; d < 128; d += 64) {
        float v = bv[d] * csum;
#pragma unroll
        for (int q = 0; q < 7; q++) v += Wv[d * 7 + q] * s_red[4 + q];
        g_CAT[(size_t)node * 256 + 128 + d] = v;
    }
}

// ---------------------------------------------------------------------------
// Deterministic entropy mean reduction
// ---------------------------------------------------------------------------
__global__ void ent_reduce(float* __restrict__ out_ent)
{
    __shared__ float s[256];
    const int t = threadIdx.x;
    float a = 0.f;
    for (int i = t; i < NNODE; i += 256) a += g_ent[i];
    s[t] = a;
    __syncthreads();
    for (int off = 128; off > 0; off >>= 1) {
        if (t < off) s[t] += s[t + off];
        __syncthreads();
    }
    if (t == 0) out_ent[0] = s[0] / (float)NNODE;
}

// ---------------------------------------------------------------------------
// Host launch
// ---------------------------------------------------------------------------
extern "C" void kernel_launch(void* const* d_in, const int* in_sizes, int n_in,
                              void* d_out, int out_size)
{
    const float* emb = (const float*)d_in[0];
    const float* gum = (const float*)d_in[1];
    const float* W1  = (const float*)d_in[2];
    const float* b1  = (const float*)d_in[3];
    const float* W2  = (const float*)d_in[4];
    const float* b2  = (const float*)d_in[5];
    const float* Wh1 = (const float*)d_in[6];
    const float* bh1 = (const float*)d_in[7];
    const float* Wh2 = (const float*)d_in[8];
    const float* bh2 = (const float*)d_in[9];
    const float* Whe = (const float*)d_in[10];
    const float* bhe = (const float*)d_in[11];
    const float* Wq  = (const float*)d_in[12];
    const float* Wa1 = (const float*)d_in[13];
    const float* ba1 = (const float*)d_in[14];
    const float* Wa2 = (const float*)d_in[15];
    const float* ba2 = (const float*)d_in[16];
    const float* Wv  = (const float*)d_in[17];
    const float* bv  = (const float*)d_in[18];
    const float* Wd1 = (const float*)d_in[19];
    const float* bd1 = (const float*)d_in[20];
    const float* Wd2 = (const float*)d_in[21];
    const float* bd2 = (const float*)d_in[22];

    float* out      = (float*)d_out;
    float* out_att  = out;                      // 8192*256
    float* out_log  = out_att + 2097152;        // 8192*63
    float* out_dist = out_log + 516096;         // 8192*63
    float* out_ent  = out_dist + 516096;        // 1
    float* out_hw   = out_ent + 1;              // 8192*63
    float* out_cmb  = out_hw + 516096;          // 8192*63

    float *H, *CAT, *PP, *D1, *Wpp, *bpp;
    cudaGetSymbolAddress((void**)&H,   g_H);
    cudaGetSymbolAddress((void**)&CAT, g_CAT);
    cudaGetSymbolAddress((void**)&PP,  g_PP);
    cudaGetSymbolAddress((void**)&D1,  g_D1);
    cudaGetSymbolAddress((void**)&Wpp, g_Wpp);
    cudaGetSymbolAddress((void**)&bpp, g_bpp);

    // Folded weights (must precede G3 + edge kernel)
    precompute<<<257, 128>>>(Wh1, Wa1, Wq, Whe, Wh2, bh2, bhe, bh1, ba1);

    // Node pipeline
    // G1: H = lrelu(embed @ W1^T + b1); embed = embedding[:, 4:9] (lda=9, ptr+4)
    gemm_act<<<dim3(2, 128), 256>>>(emb + 4, 9, W1, 5, b1, H, 128, NNODE, 128, 5, 1);
    // G2: AE = lrelu(H @ W2^T + b2) -> CAT[:, :128]
    gemm_act<<<dim3(2, 128), 256>>>(H, 128, W2, 128, b2, CAT, 256, NNODE, 128, 128, 1);
    // G3: [P1 | Pa] = AE @ Wpp^T + bpp
    gemm_act<<<dim3(4, 128), 256>>>(CAT, 256, Wpp, 128, bpp, PP, 256, NNODE, 256, 128, 0);

    // Edge pipeline (writes 4 output regions + CAT[:, 128:])
    edge_kernel<<<NNODE, 64>>>(emb, gum, Wa2, ba2, Wv, bv,
                               out_log, out_dist, out_hw, out_cmb);

    ent_reduce<<<1, 256>>>(out_ent);

    // Decoder
    gemm_act<<<dim3(4, 128), 256>>>(CAT, 256, Wd1, 256, bd1, D1, 256, NNODE, 256, 256, 1);
    gemm_act<<<dim3(4, 128), 256>>>(D1, 256, Wd2, 256, bd2, out_att, 256, NNODE, 256, 256, 1);

    (void)in_sizes; (void)n_in; (void)out_size;
}

// round 5
// speedup vs baseline: 1.4490x; 1.4398x over previous
#include <cuda_runtime.h>
#include <math.h>

// ---------------------------------------------------------------------------
// Problem constants
// ---------------------------------------------------------------------------
#define BB   128
#define NN   64
#define EE   128
#define NNODE (BB*NN)          // 8192
#define NEDGE (NN-1)           // 63

// ---------------------------------------------------------------------------
// Device scratch (static, no allocation)
// ---------------------------------------------------------------------------
__device__ __align__(16) float g_H  [NNODE*128];   // hidden after W1
__device__ __align__(16) float g_CAT[NNODE*256];   // [ae | attn_out]
__device__ __align__(16) float g_PP [NNODE*256];   // [P1 | Pa]
__device__ __align__(16) float g_D1 [NNODE*256];   // hidden after Wd1
__device__ __align__(16) float g_Wpp[256*128];     // rows 0..127: Wh1[:, :128]; 128..255: Wa1[:, :128]@Wq
__device__ __align__(16) float g_bpp[256];         // [bh1 | ba1]
__device__ __align__(16) float g_Wc [2*128];       // Whe @ Wh2
__device__ __align__(16) float g_bc [2];           // Whe @ bh2 + bhe
__device__ __align__(16) float g_Wh1e[128*8];      // Wh1[:, 128:135], padded to 8
__device__ __align__(16) float g_Wa1e[128*8];      // Wa1[:, 128:135], padded to 8
__device__ float g_ent[NNODE];

// ---------------------------------------------------------------------------
// Fused GEMM:  C = act(A @ W^T + bias)
// Block tile 128(M) x 64(N), 256 threads, 8x4 per thread, k-major smem,
// float4 fragment loads. M % 128 == 0, N % 64 == 0 assumed.
// act: 0 = none, 1 = leaky_relu(0.01)
// ---------------------------------------------------------------------------
#define KT 16
__global__ __launch_bounds__(256) void gemm_act(
    const float* __restrict__ A, int lda,
    const float* __restrict__ W, int ldw,
    const float* __restrict__ bias,
    float* __restrict__ C, int ldc,
    int M, int N, int K, int act)
{
    __shared__ __align__(16) float As[KT][132];   // [kk][row]
    __shared__ __align__(16) float Ws[KT][68];    // [kk][col]
    const int tid = threadIdx.x;
    const int bm = blockIdx.y * 128;
    const int bn = blockIdx.x * 64;
    const int tm = (tid >> 4) * 8;   // 0..120
    const int tn = (tid & 15) * 4;   // 0..60

    float acc[8][4];
#pragma unroll
    for (int i = 0; i < 8; i++)
#pragma unroll
        for (int j = 0; j < 4; j++) acc[i][j] = 0.f;

    for (int k0 = 0; k0 < K; k0 += KT) {
        // A tile: 128 rows x 16 k = 2048 elems (8/thread), stored k-major
#pragma unroll
        for (int i = 0; i < 8; i++) {
            int idx = tid + i * 256;
            int r = idx >> 4, kk = idx & 15;
            int kg = k0 + kk;
            As[kk][r] = (kg < K) ? A[(size_t)(bm + r) * lda + kg] : 0.f;
        }
        // W tile: 64 cols x 16 k = 1024 elems (4/thread), k-major
#pragma unroll
        for (int i = 0; i < 4; i++) {
            int idx = tid + i * 256;
            int c = idx >> 4, kk = idx & 15;
            int kg = k0 + kk;
            Ws[kk][c] = (kg < K) ? W[(size_t)(bn + c) * ldw + kg] : 0.f;
        }
        __syncthreads();
#pragma unroll
        for (int kk = 0; kk < KT; kk++) {
            const float4 af0 = *(const float4*)&As[kk][tm];
            const float4 af1 = *(const float4*)&As[kk][tm + 4];
            const float4 wf  = *(const float4*)&Ws[kk][tn];
            const float a[8] = {af0.x, af0.y, af0.z, af0.w,
                                af1.x, af1.y, af1.z, af1.w};
            const float wv[4] = {wf.x, wf.y, wf.z, wf.w};
#pragma unroll
            for (int i = 0; i < 8; i++)
#pragma unroll
                for (int j = 0; j < 4; j++)
                    acc[i][j] = fmaf(a[i], wv[j], acc[i][j]);
        }
        __syncthreads();
    }

    // epilogue: bias + activation, vectorized store
    float bvv[4] = {0.f, 0.f, 0.f, 0.f};
    if (bias) {
        const float4 b4 = *(const float4*)&bias[bn + tn];
        bvv[0] = b4.x; bvv[1] = b4.y; bvv[2] = b4.z; bvv[3] = b4.w;
    }
#pragma unroll
    for (int i = 0; i < 8; i++) {
        float4 o;
        float* op = (float*)&o;
#pragma unroll
        for (int j = 0; j < 4; j++) {
            float v = acc[i][j] + bvv[j];
            if (act == 1) v = (v > 0.f) ? v : 0.01f * v;
            op[j] = v;
        }
        *(float4*)&C[(size_t)(bm + tm + i) * ldc + (bn + tn)] = o;
    }
}

// ---------------------------------------------------------------------------
// Precompute folded weights (runs every launch; deterministic, ~2 MFLOP)
// ---------------------------------------------------------------------------
__global__ void precompute(
    const float* __restrict__ Wh1, const float* __restrict__ Wa1,
    const float* __restrict__ Wq,  const float* __restrict__ Whe,
    const float* __restrict__ Wh2, const float* __restrict__ bh2,
    const float* __restrict__ bhe, const float* __restrict__ bh1,
    const float* __restrict__ ba1)
{
    const int b = blockIdx.x, t = threadIdx.x;   // 128 threads
    if (b < 128) {
        g_Wpp[b * 128 + t] = Wh1[b * 135 + t];
    } else if (b < 256) {
        const int o = b - 128;
        float acc = 0.f;
        for (int j = 0; j < 128; j++) acc += Wa1[o * 135 + j] * Wq[j * 128 + t];
        g_Wpp[b * 128 + t] = acc;
    } else {
        float a0 = 0.f, a1 = 0.f;
        for (int j = 0; j < 128; j++) {
            a0 += Whe[j]       * Wh2[j * 128 + t];
            a1 += Whe[128 + j] * Wh2[j * 128 + t];
        }
        g_Wc[t] = a0; g_Wc[128 + t] = a1;
        if (t < 2) {
            float s = 0.f;
            for (int j = 0; j < 128; j++) s += Whe[t * 128 + j] * bh2[j];
            g_bc[t] = s + bhe[t];
        }
        g_bpp[t] = bh1[t]; g_bpp[128 + t] = ba1[t];
#pragma unroll
        for (int j = 0; j < 8; j++) {
            g_Wh1e[t * 8 + j] = (j < 7) ? Wh1[t * 135 + 128 + j] : 0.f;
            g_Wa1e[t * 8 + j] = (j < 7) ? Wa1[t * 135 + 128 + j] : 0.f;
        }
    }
}

// ---------------------------------------------------------------------------
// Warp reduction helpers (fixed shuffle trees -> deterministic)
// ---------------------------------------------------------------------------
__device__ __forceinline__ float warp_sum(float v) {
#pragma unroll
    for (int o = 16; o > 0; o >>= 1) v += __shfl_xor_sync(0xffffffffu, v, o);
    return v;
}
__device__ __forceinline__ float warp_max(float v) {
#pragma unroll
    for (int o = 16; o > 0; o >>= 1) v = fmaxf(v, __shfl_xor_sync(0xffffffffu, v, o));
    return v;
}

// ---------------------------------------------------------------------------
// Fused per-edge kernel: one block (64 threads = 2 warps) per node.
// Vectorized float4 weight reads; warp-shuffle reductions (no serial loops).
// e[7] := 1 (weight pad is 0) so the c*e reduction yields csum for free.
// ---------------------------------------------------------------------------
__global__ __launch_bounds__(64) void edge_kernel(
    const float* __restrict__ emb,   // (8192, 9)
    const float* __restrict__ gum,   // (8192, 63, 2)
    const float* __restrict__ Wa2,   // (1,128)
    const float* __restrict__ ba2,   // (1,)
    const float* __restrict__ Wv,    // (128,7)
    const float* __restrict__ bv,    // (128,)
    float* __restrict__ out_log,
    float* __restrict__ out_dist,
    float* __restrict__ out_hw,
    float* __restrict__ out_cmb)
{
    __shared__ __align__(16) float PPs[256];      // [P1 | Pa]
    __shared__ __align__(16) float Wcs[256];      // [Wc0 | Wc1]
    __shared__ __align__(16) float Wa2s[128];
    __shared__ __align__(16) float Wh1e_s[1024];
    __shared__ __align__(16) float Wa1e_s[1024];
    __shared__ __align__(16) float Wvs[896];
    __shared__ __align__(16) float bvs[128];
    __shared__ float s_emb[576];                  // 64 node rows x 9
    __shared__ float s_red[4];                    // per-warp max / any
    __shared__ float s_den[2];
    __shared__ float s_v[16];                     // per-warp 8-vector partials
    __shared__ float s_ent[2];

    const int node = blockIdx.x;
    const int n = node & (NN - 1);
    const int t = threadIdx.x;
    const int wid = t >> 5, lane = t & 31;

    // ---- stage 0: cooperative loads -------------------------------------
    {
        const float4* pp = (const float4*)(g_PP + (size_t)node * 256);
        ((float4*)PPs)[t] = pp[t];                       // 64 x float4 = 256 f
        ((float4*)Wcs)[t] = ((const float4*)g_Wc)[t];    // 256 f
        if (t < 32) ((float4*)Wa2s)[t] = ((const float4*)Wa2)[t];
        for (int i = t; i < 256; i += 64) {
            ((float4*)Wh1e_s)[i] = ((const float4*)g_Wh1e)[i];
            ((float4*)Wa1e_s)[i] = ((const float4*)g_Wa1e)[i];
        }
        for (int i = t; i < 224; i += 64) ((float4*)Wvs)[i] = ((const float4*)Wv)[i];
        if (t < 32) ((float4*)bvs)[t] = ((const float4*)bv)[t];
        const float* eb = emb + (size_t)(node - n) * 9;
        for (int i = t; i < 576; i += 64) s_emb[i] = eb[i];
    }
    __syncthreads();

    // ---- stage 1: edge features -----------------------------------------
    float e[8] = {0.f, 0.f, 0.f, 0.f, 0.f, 0.f, 0.f, 1.f};
    float rd = 0.f;
    const bool act = (t < NEDGE);
    if (act) {
        const int j = t + (t >= n);
        const float* er = s_emb + n * 9;
        const float* ej = s_emb + j * 9;
        float dx = ej[0] - er[0], dy = ej[1] - er[1];
        float sq = dx * dx + dy * dy;
        rd = (sq > 0.f) ? sqrtf(sq) : 0.f;
        float ang = atan2f(dy, dx) - atan2f(er[3], er[2]);
        float ca, sa;
        sincosf(ang, &sa, &ca);
        e[0] = rd; e[1] = ca; e[2] = sa;
        e[3] = ej[2]; e[4] = ej[3]; e[5] = ej[7]; e[6] = ej[8];
    }
    const float4 ev0 = make_float4(e[0], e[1], e[2], e[3]);
    const float4 ev1 = make_float4(e[4], e[5], e[6], 0.f);

    // ---- stage 2: fused logits / score loop (vectorized) ----------------
    float l0 = 0.f, l1 = 0.f, sc = 0.f;
    const float4* wh  = (const float4*)Wh1e_s;
    const float4* wa  = (const float4*)Wa1e_s;
    const float4* p14 = (const float4*)PPs;
    const float4* pa4 = (const float4*)(PPs + 128);
    const float4* c04 = (const float4*)Wcs;
    const float4* c14 = (const float4*)(Wcs + 128);
    const float4* a24 = (const float4*)Wa2s;

    for (int oc = 0; oc < 32; oc++) {
        const float4 p1 = p14[oc], pa = pa4[oc];
        const float4 c0 = c04[oc], c1 = c14[oc], w2 = a24[oc];
        const float phv[4] = {p1.x, p1.y, p1.z, p1.w};
        const float pav[4] = {pa.x, pa.y, pa.z, pa.w};
        const float c0v[4] = {c0.x, c0.y, c0.z, c0.w};
        const float c1v[4] = {c1.x, c1.y, c1.z, c1.w};
        const float w2v[4] = {w2.x, w2.y, w2.z, w2.w};
#pragma unroll
        for (int s = 0; s < 4; s++) {
            const int o = oc * 4 + s;
            const float4 h0 = wh[2 * o], h1 = wh[2 * o + 1];
            const float4 q0 = wa[2 * o], q1 = wa[2 * o + 1];
            float h = phv[s];
            h = fmaf(h0.x, ev0.x, h); h = fmaf(h0.y, ev0.y, h);
            h = fmaf(h0.z, ev0.z, h); h = fmaf(h0.w, ev0.w, h);
            h = fmaf(h1.x, ev1.x, h); h = fmaf(h1.y, ev1.y, h);
            h = fmaf(h1.z, ev1.z, h);
            float a = pav[s];
            a = fmaf(q0.x, ev0.x, a); a = fmaf(q0.y, ev0.y, a);
            a = fmaf(q0.z, ev0.z, a); a = fmaf(q0.w, ev0.w, a);
            a = fmaf(q1.x, ev1.x, a); a = fmaf(q1.y, ev1.y, a);
            a = fmaf(q1.z, ev1.z, a);
            h = fmaxf(h, 0.f); a = fmaxf(a, 0.f);
            l0 = fmaf(c0v[s], h, l0);
            l1 = fmaf(c1v[s], h, l1);
            sc = fmaf(w2v[s], a, sc);
        }
    }
    l0 += g_bc[0]; l1 += g_bc[1]; sc += ba2[0];

    // ---- stage 3: gumbel softmax, outputs -------------------------------
    float m = 0.f;
    if (act) {
        const size_t gi = ((size_t)node * NEDGE + t) * 2;
        const float2 g = *(const float2*)(gum + gi);
        const float y1 = 1.f / (1.f + expf(2.f * ((l0 + g.x) - (l1 + g.y))));
        m = (y1 > 0.5f) ? 1.f : 0.f;
        const size_t oi = (size_t)node * NEDGE + t;
        out_log[oi]  = l1;
        out_dist[oi] = 12.f * rd;
        out_hw[oi]   = y1;
    }

    // ---- stage 4: masked softmax via warp reductions --------------------
    const float mval = (m > 0.f) ? sc : -1e30f;
    const float wm = warp_max(mval);
    const float wany = warp_max(m);
    if (lane == 0) { s_red[wid] = wm; s_red[2 + wid] = wany; }
    __syncthreads();
    const float maxv = fmaxf(s_red[0], s_red[1]);
    const bool anyb = (fmaxf(s_red[2], s_red[3]) > 0.f);
    const float ex = (m > 0.f) ? expf(sc - maxv) : 0.f;
    const float ds = warp_sum(ex);
    if (lane == 0) s_den[wid] = ds;
    __syncthreads();
    const float den = s_den[0] + s_den[1];
    const float c = (anyb && m > 0.f) ? ex / den : 0.f;
    if (act) out_cmb[(size_t)node * NEDGE + t] = c;

    // ---- stage 5: weighted edge-feature sums (v[7] = csum) --------------
    float v[8];
#pragma unroll
    for (int q = 0; q < 8; q++) v[q] = warp_sum(c * e[q]);
    if (lane == 0) {
#pragma unroll
        for (int q = 0; q < 8; q++) s_v[wid * 8 + q] = v[q];
    }
    __syncthreads();
    const float csum = s_v[7] + s_v[15];

    // ---- stage 6: entropy -----------------------------------------------
    const float inv = 1.f / (csum + 1e-6f);
    const float cw = c * inv;
    const float es = warp_sum(-cw * logf(cw + 1e-6f));
    if (lane == 0) s_ent[wid] = es;
    __syncthreads();
    if (t == 0) g_ent[node] = s_ent[0] + s_ent[1];

    // ---- stage 7: attn_out = Wv @ esum + bv * csum ----------------------
#pragma unroll
    for (int rr = 0; rr < 2; rr++) {
        const int d = t + rr * 64;
        float vv = bvs[d] * csum;
#pragma unroll
        for (int q = 0; q < 7; q++)
            vv = fmaf(Wvs[d * 7 + q], s_v[q] + s_v[8 + q], vv);
        g_CAT[(size_t)node * 256 + 128 + d] = vv;
    }
}

// ---------------------------------------------------------------------------
// Deterministic entropy mean reduction
// ---------------------------------------------------------------------------
__global__ void ent_reduce(float* __restrict__ out_ent)
{
    __shared__ float s[256];
    const int t = threadIdx.x;
    float a = 0.f;
    for (int i = t; i < NNODE; i += 256) a += g_ent[i];
    s[t] = a;
    __syncthreads();
    for (int off = 128; off > 0; off >>= 1) {
        if (t < off) s[t] += s[t + off];
        __syncthreads();
    }
    if (t == 0) out_ent[0] = s[0] / (float)NNODE;
}

// ---------------------------------------------------------------------------
// Host launch
// ---------------------------------------------------------------------------
extern "C" void kernel_launch(void* const* d_in, const int* in_sizes, int n_in,
                              void* d_out, int out_size)
{
    const float* emb = (const float*)d_in[0];
    const float* gum = (const float*)d_in[1];
    const float* W1  = (const float*)d_in[2];
    const float* b1  = (const float*)d_in[3];
    const float* W2  = (const float*)d_in[4];
    const float* b2  = (const float*)d_in[5];
    const float* Wh1 = (const float*)d_in[6];
    const float* bh1 = (const float*)d_in[7];
    const float* Wh2 = (const float*)d_in[8];
    const float* bh2 = (const float*)d_in[9];
    const float* Whe = (const float*)d_in[10];
    const float* bhe = (const float*)d_in[11];
    const float* Wq  = (const float*)d_in[12];
    const float* Wa1 = (const float*)d_in[13];
    const float* ba1 = (const float*)d_in[14];
    const float* Wa2 = (const float*)d_in[15];
    const float* ba2 = (const float*)d_in[16];
    const float* Wv  = (const float*)d_in[17];
    const float* bv  = (const float*)d_in[18];
    const float* Wd1 = (const float*)d_in[19];
    const float* bd1 = (const float*)d_in[20];
    const float* Wd2 = (const float*)d_in[21];
    const float* bd2 = (const float*)d_in[22];

    float* out      = (float*)d_out;
    float* out_att  = out;                      // 8192*256
    float* out_log  = out_att + 2097152;        // 8192*63
    float* out_dist = out_log + 516096;         // 8192*63
    float* out_ent  = out_dist + 516096;        // 1
    float* out_hw   = out_ent + 1;              // 8192*63
    float* out_cmb  = out_hw + 516096;          // 8192*63

    float *H, *CAT, *PP, *D1, *Wpp, *bpp;
    cudaGetSymbolAddress((void**)&H,   g_H);
    cudaGetSymbolAddress((void**)&CAT, g_CAT);
    cudaGetSymbolAddress((void**)&PP,  g_PP);
    cudaGetSymbolAddress((void**)&D1,  g_D1);
    cudaGetSymbolAddress((void**)&Wpp, g_Wpp);
    cudaGetSymbolAddress((void**)&bpp, g_bpp);

    // Folded weights (must precede G3 + edge kernel)
    precompute<<<257, 128>>>(Wh1, Wa1, Wq, Whe, Wh2, bh2, bhe, bh1, ba1);

    // Node pipeline (grid = (N/64, M/128))
    // G1: H = lrelu(embed @ W1^T + b1); embed = embedding[:, 4:9]
    gemm_act<<<dim3(2, 64), 256>>>(emb + 4, 9, W1, 5, b1, H, 128, NNODE, 128, 5, 1);
    // G2: AE = lrelu(H @ W2^T + b2) -> CAT[:, :128]
    gemm_act<<<dim3(2, 64), 256>>>(H, 128, W2, 128, b2, CAT, 256, NNODE, 128, 128, 1);
    // G3: [P1 | Pa] = AE @ Wpp^T + bpp
    gemm_act<<<dim3(4, 64), 256>>>(CAT, 256, Wpp, 128, bpp, PP, 256, NNODE, 256, 128, 0);

    // Edge pipeline (writes 4 output regions + CAT[:, 128:])
    edge_kernel<<<NNODE, 64>>>(emb, gum, Wa2, ba2, Wv, bv,
                               out_log, out_dist, out_hw, out_cmb);

    ent_reduce<<<1, 256>>>(out_ent);

    // Decoder
    gemm_act<<<dim3(4, 64), 256>>>(CAT, 256, Wd1, 256, bd1, D1, 256, NNODE, 256, 256, 1);
    gemm_act<<<dim3(4, 64), 256>>>(D1, 256, Wd2, 256, bd2, out_att, 256, NNODE, 256, 256, 1);

    (void)in_sizes; (void)n_in; (void)out_size;
}